// round 1
// baseline (speedup 1.0000x reference)
#include <cuda_runtime.h>

#define HH 512
#define WW 512
#define NPIX (HH*WW)
#define BSZ 64
#define PIX_PER_THREAD 4
#define THREADS 256

// Per-batch fused transform: A (3x3, row-major A[c][d]) followed by bias (3)
__device__ float g_AB[BSZ * 12];

__global__ void precompute_kernel(const float* __restrict__ R0g,
                                  const float* __restrict__ t0g,
                                  const float* __restrict__ R1g,
                                  const float* __restrict__ t1g,
                                  const float* __restrict__ Kg)
{
    int b = threadIdx.x;
    if (b >= BSZ) return;

    float R0[9], R1[9], Kl[9], t0[3], t1[3];
    #pragma unroll
    for (int i = 0; i < 9; i++) {
        R0[i] = R0g[b * 9 + i];
        R1[i] = R1g[b * 9 + i];
        Kl[i] = Kg[i];
    }
    #pragma unroll
    for (int i = 0; i < 3; i++) {
        t0[i] = t0g[b * 3 + i];
        t1[i] = t1g[b * 3 + i];
    }

    // M = R0 @ R1^T : M[c][d] = sum_e R0[c][e] * R1[d][e]
    float M[9];
    #pragma unroll
    for (int c = 0; c < 3; c++)
        #pragma unroll
        for (int d = 0; d < 3; d++)
            M[c * 3 + d] = R0[c * 3 + 0] * R1[d * 3 + 0]
                         + R0[c * 3 + 1] * R1[d * 3 + 1]
                         + R0[c * 3 + 2] * R1[d * 3 + 2];

    // A = M @ K^T : A[c][d] = sum_e M[c][e] * K[d][e]
    float A[9];
    #pragma unroll
    for (int c = 0; c < 3; c++)
        #pragma unroll
        for (int d = 0; d < 3; d++)
            A[c * 3 + d] = M[c * 3 + 0] * Kl[d * 3 + 0]
                         + M[c * 3 + 1] * Kl[d * 3 + 1]
                         + M[c * 3 + 2] * Kl[d * 3 + 2];

    // bias[d] = sum_e t1[e]*K[d][e] - sum_c t0[c]*A[c][d]
    float bias[3];
    #pragma unroll
    for (int d = 0; d < 3; d++) {
        float tb = t1[0] * Kl[d * 3 + 0] + t1[1] * Kl[d * 3 + 1] + t1[2] * Kl[d * 3 + 2];
        tb -= t0[0] * A[0 * 3 + d] + t0[1] * A[1 * 3 + d] + t0[2] * A[2 * 3 + d];
        bias[d] = tb;
    }

    #pragma unroll
    for (int i = 0; i < 9; i++) g_AB[b * 12 + i] = A[i];
    #pragma unroll
    for (int i = 0; i < 3; i++) g_AB[b * 12 + 9 + i] = bias[i];
}

__global__ __launch_bounds__(THREADS) void uv_transform_kernel(
    const float* __restrict__ depth,
    const float* __restrict__ ray,
    float* __restrict__ uv_out,
    float* __restrict__ d_out)
{
    const int b = blockIdx.y;

    __shared__ float s[12];
    if (threadIdx.x < 12) s[threadIdx.x] = g_AB[b * 12 + threadIdx.x];
    __syncthreads();

    const int p0 = (blockIdx.x * THREADS + threadIdx.x) * PIX_PER_THREAD;
    if (p0 >= NPIX) return;

    // Registers for the fused transform
    const float A00 = s[0], A01 = s[1], A02 = s[2];
    const float A10 = s[3], A11 = s[4], A12 = s[5];
    const float A20 = s[6], A21 = s[7], A22 = s[8];
    const float b0 = s[9], b1 = s[10], b2 = s[11];

    // depth: 1x float4 (coalesced)
    const float4 dep = *reinterpret_cast<const float4*>(depth + (size_t)b * NPIX + p0);

    // ray: 3x float4 = 12 floats for 4 pixels (16B aligned: p0 % 4 == 0)
    const float4* rv = reinterpret_cast<const float4*>(ray + (size_t)p0 * 3);
    const float4 ra = rv[0];
    const float4 rb = rv[1];
    const float4 rc = rv[2];

    const float rx[4] = {ra.x, ra.w, rb.z, rc.y};
    const float ry[4] = {ra.y, rb.x, rb.w, rc.z};
    const float rz[4] = {ra.z, rb.y, rc.x, rc.w};
    const float dv[4] = {dep.x, dep.y, dep.z, dep.w};

    float u[4], v[4], dd[4];
    #pragma unroll
    for (int i = 0; i < PIX_PER_THREAD; i++) {
        // r = ray @ A
        const float r0 = rx[i] * A00 + ry[i] * A10 + rz[i] * A20;
        const float r1 = rx[i] * A01 + ry[i] * A11 + rz[i] * A21;
        const float r2 = rx[i] * A02 + ry[i] * A12 + rz[i] * A22;
        // uv3 = depth * r + bias
        const float u3 = fmaf(dv[i], r0, b0);
        const float v3 = fmaf(dv[i], r1, b1);
        const float w3 = fmaf(dv[i], r2, b2);
        dd[i] = w3;
        const float den = fmaxf(w3, 0.0f) + 1e-12f;
        u[i] = __fdividef(u3, den);
        v[i] = __fdividef(v3, den);
    }

    // uv: (BS, N, 2) interleaved -> 2x float4 per thread
    const size_t uvbase = ((size_t)b * NPIX + p0) * 2;
    float4 uvA, uvB;
    uvA.x = u[0]; uvA.y = v[0]; uvA.z = u[1]; uvA.w = v[1];
    uvB.x = u[2]; uvB.y = v[2]; uvB.z = u[3]; uvB.w = v[3];
    *reinterpret_cast<float4*>(uv_out + uvbase)     = uvA;
    *reinterpret_cast<float4*>(uv_out + uvbase + 4) = uvB;

    // d: (BS, N, 1) -> 1x float4
    float4 dq;
    dq.x = dd[0]; dq.y = dd[1]; dq.z = dd[2]; dq.w = dd[3];
    *reinterpret_cast<float4*>(d_out + (size_t)b * NPIX + p0) = dq;
}

extern "C" void kernel_launch(void* const* d_in, const int* in_sizes, int n_in,
                              void* d_out, int out_size)
{
    // metadata order: depth0, R0, t0, R1, t1, K, ray
    const float* depth = (const float*)d_in[0];
    const float* R0    = (const float*)d_in[1];
    const float* t0    = (const float*)d_in[2];
    const float* R1    = (const float*)d_in[3];
    const float* t1    = (const float*)d_in[4];
    const float* K     = (const float*)d_in[5];
    const float* ray   = (const float*)d_in[6];

    float* uv_out = (float*)d_out;                       // BS*N*2 floats
    float* dd_out = (float*)d_out + (size_t)BSZ * NPIX * 2;  // BS*N floats

    precompute_kernel<<<1, BSZ>>>(R0, t0, R1, t1, K);

    dim3 grid(NPIX / (THREADS * PIX_PER_THREAD), BSZ);
    uv_transform_kernel<<<grid, THREADS>>>(depth, ray, uv_out, dd_out);
}

// round 2
// speedup vs baseline: 1.2257x; 1.2257x over previous
#include <cuda_runtime.h>

#define HH 512
#define WW 512
#define NPIX (HH*WW)
#define BSZ 64
#define PIX_PER_THREAD 4
#define THREADS 256

// Per-batch fused transform: B (3x3, row-major: r_d = col*B[0][d] + row*B[1][d] + B[2][d])
// followed by bias (3).
__device__ float g_AB[BSZ * 12];

__global__ void precompute_kernel(const float* __restrict__ R0g,
                                  const float* __restrict__ t0g,
                                  const float* __restrict__ R1g,
                                  const float* __restrict__ t1g,
                                  const float* __restrict__ Kg)
{
    int b = threadIdx.x;
    if (b >= BSZ) return;

    float R0[9], R1[9], Kl[9], t0[3], t1[3];
    #pragma unroll
    for (int i = 0; i < 9; i++) {
        R0[i] = R0g[b * 9 + i];
        R1[i] = R1g[b * 9 + i];
        Kl[i] = Kg[i];
    }
    #pragma unroll
    for (int i = 0; i < 3; i++) {
        t0[i] = t0g[b * 3 + i];
        t1[i] = t1g[b * 3 + i];
    }

    // Ki = inv(K) via adjugate (double precision for safety; runs once on 64 threads)
    double k00 = Kl[0], k01 = Kl[1], k02 = Kl[2];
    double k10 = Kl[3], k11 = Kl[4], k12 = Kl[5];
    double k20 = Kl[6], k21 = Kl[7], k22 = Kl[8];
    double det = k00*(k11*k22 - k12*k21) - k01*(k10*k22 - k12*k20) + k02*(k10*k21 - k11*k20);
    double inv = 1.0 / det;
    float Ki[9];
    Ki[0] = (float)(( k11*k22 - k12*k21) * inv);
    Ki[1] = (float)((-k01*k22 + k02*k21) * inv);
    Ki[2] = (float)(( k01*k12 - k02*k11) * inv);
    Ki[3] = (float)((-k10*k22 + k12*k20) * inv);
    Ki[4] = (float)(( k00*k22 - k02*k20) * inv);
    Ki[5] = (float)((-k00*k12 + k02*k10) * inv);
    Ki[6] = (float)(( k10*k21 - k11*k20) * inv);
    Ki[7] = (float)((-k00*k21 + k01*k20) * inv);
    Ki[8] = (float)(( k00*k11 - k01*k10) * inv);

    // M = R0 @ R1^T : M[c][d] = sum_e R0[c][e] * R1[d][e]
    float M[9];
    #pragma unroll
    for (int c = 0; c < 3; c++)
        #pragma unroll
        for (int d = 0; d < 3; d++)
            M[c * 3 + d] = R0[c * 3 + 0] * R1[d * 3 + 0]
                         + R0[c * 3 + 1] * R1[d * 3 + 1]
                         + R0[c * 3 + 2] * R1[d * 3 + 2];

    // A = M @ K^T : A[c][d] = sum_e M[c][e] * K[d][e]
    float A[9];
    #pragma unroll
    for (int c = 0; c < 3; c++)
        #pragma unroll
        for (int d = 0; d < 3; d++)
            A[c * 3 + d] = M[c * 3 + 0] * Kl[d * 3 + 0]
                         + M[c * 3 + 1] * Kl[d * 3 + 1]
                         + M[c * 3 + 2] * Kl[d * 3 + 2];

    // bias[d] = sum_e t1[e]*K[d][e] - sum_c t0[c]*A[c][d]
    float bias[3];
    #pragma unroll
    for (int d = 0; d < 3; d++) {
        float tb = t1[0] * Kl[d * 3 + 0] + t1[1] * Kl[d * 3 + 1] + t1[2] * Kl[d * 3 + 2];
        tb -= t0[0] * A[0 * 3 + d] + t0[1] * A[1 * 3 + d] + t0[2] * A[2 * 3 + d];
        bias[d] = tb;
    }

    // B = Ki^T @ A : B[m][d] = sum_k Ki[k][m] * A[k][d]
    // (ray = Ki @ (col,row,1), so r_d = sum_k ray_k A[k][d] = col*B[0][d]+row*B[1][d]+B[2][d])
    float B[9];
    #pragma unroll
    for (int m = 0; m < 3; m++)
        #pragma unroll
        for (int d = 0; d < 3; d++)
            B[m * 3 + d] = Ki[0 * 3 + m] * A[0 * 3 + d]
                         + Ki[1 * 3 + m] * A[1 * 3 + d]
                         + Ki[2 * 3 + m] * A[2 * 3 + d];

    #pragma unroll
    for (int i = 0; i < 9; i++) g_AB[b * 12 + i] = B[i];
    #pragma unroll
    for (int i = 0; i < 3; i++) g_AB[b * 12 + 9 + i] = bias[i];
}

__global__ __launch_bounds__(THREADS) void uv_transform_kernel(
    const float* __restrict__ depth,
    float* __restrict__ uv_out,
    float* __restrict__ d_out)
{
    const int b = blockIdx.y;

    __shared__ float s[12];
    if (threadIdx.x < 12) s[threadIdx.x] = g_AB[b * 12 + threadIdx.x];
    __syncthreads();

    const int p0 = (blockIdx.x * THREADS + threadIdx.x) * PIX_PER_THREAD;

    const float B00 = s[0], B01 = s[1], B02 = s[2];   // per-col increments
    const float B10 = s[3], B11 = s[4], B12 = s[5];   // per-row coeffs
    const float B20 = s[6], B21 = s[7], B22 = s[8];   // constant
    const float b0 = s[9], b1 = s[10], b2 = s[11];

    // depth: 1x float4 (coalesced, p0 % 4 == 0)
    const float4 dep = *reinterpret_cast<const float4*>(depth + (size_t)b * NPIX + p0);
    const float dv[4] = {dep.x, dep.y, dep.z, dep.w};

    // pixel coords: 4 consecutive pixels share a row (512 % 4 == 0)
    const float row = (float)(p0 >> 9);
    const float col = (float)(p0 & 511);

    float r0 = fmaf(col, B00, fmaf(row, B10, B20));
    float r1 = fmaf(col, B01, fmaf(row, B11, B21));
    float r2 = fmaf(col, B02, fmaf(row, B12, B22));

    float u[4], v[4], dd[4];
    #pragma unroll
    for (int i = 0; i < PIX_PER_THREAD; i++) {
        const float u3 = fmaf(dv[i], r0, b0);
        const float v3 = fmaf(dv[i], r1, b1);
        const float w3 = fmaf(dv[i], r2, b2);
        dd[i] = w3;
        const float rcp = __frcp_rn(fmaxf(w3, 0.0f) + 1e-12f);
        u[i] = u3 * rcp;
        v[i] = v3 * rcp;
        r0 += B00; r1 += B01; r2 += B02;  // advance one column
    }

    // uv: (BS, N, 2) interleaved -> 2x float4 per thread
    const size_t uvbase = ((size_t)b * NPIX + p0) * 2;
    float4 uvA, uvB;
    uvA.x = u[0]; uvA.y = v[0]; uvA.z = u[1]; uvA.w = v[1];
    uvB.x = u[2]; uvB.y = v[2]; uvB.z = u[3]; uvB.w = v[3];
    *reinterpret_cast<float4*>(uv_out + uvbase)     = uvA;
    *reinterpret_cast<float4*>(uv_out + uvbase + 4) = uvB;

    // d: (BS, N, 1) -> 1x float4
    float4 dq;
    dq.x = dd[0]; dq.y = dd[1]; dq.z = dd[2]; dq.w = dd[3];
    *reinterpret_cast<float4*>(d_out + (size_t)b * NPIX + p0) = dq;
}

extern "C" void kernel_launch(void* const* d_in, const int* in_sizes, int n_in,
                              void* d_out, int out_size)
{
    // metadata order: depth0, R0, t0, R1, t1, K, ray
    const float* depth = (const float*)d_in[0];
    const float* R0    = (const float*)d_in[1];
    const float* t0    = (const float*)d_in[2];
    const float* R1    = (const float*)d_in[3];
    const float* t1    = (const float*)d_in[4];
    const float* K     = (const float*)d_in[5];

    float* uv_out = (float*)d_out;                           // BS*N*2 floats
    float* dd_out = (float*)d_out + (size_t)BSZ * NPIX * 2;  // BS*N floats

    precompute_kernel<<<1, BSZ>>>(R0, t0, R1, t1, K);

    dim3 grid(NPIX / (THREADS * PIX_PER_THREAD), BSZ);
    uv_transform_kernel<<<grid, THREADS>>>(depth, uv_out, dd_out);
}